// round 14
// baseline (speedup 1.0000x reference)
#include <cuda_runtime.h>
#include <math.h>

#define Bv 64
#define Tv 512
#define Dv 512
#define Hv 1024
#define FH 4096            // 4*H
#define NTv (Bv*Tv)        // 32768
#define RBLK 128
#define RTHR 256
#define RSMEM (Hv*32*4)    // 128 KB resident weight slice

// ---------------- scratch (device globals; no dynamic allocation allowed) ----------------
__device__ float    g_xz[(size_t)NTv * FH];   // 512 MB: x-part preactivations, gate-interleaved cols (4u+g)
__device__ float    g_y0[(size_t)NTv * Hv];   // 128 MB: layer-0 output sequence
__device__ float    g_hbuf[2][Hv][Bv];        // double-buffered h state, [unit][batch]
__device__ unsigned g_arrive = 0;
__device__ unsigned g_gen    = 0;

// ---------------- f32x2 helpers (packed fp32 pipe: 2x FFMA throughput) ----------------
__device__ __forceinline__ unsigned long long splat2(float x) {
    unsigned long long r;
    asm("mov.b64 %0, {%1, %1};" : "=l"(r) : "f"(x));
    return r;
}
__device__ __forceinline__ unsigned long long pack2(float lo, float hi) {
    unsigned long long r;
    asm("mov.b64 %0, {%1, %2};" : "=l"(r) : "f"(lo), "f"(hi));
    return r;
}
__device__ __forceinline__ float2 unpk2(unsigned long long v) {
    float2 r;
    asm("mov.b64 {%0, %1}, %2;" : "=f"(r.x), "=f"(r.y) : "l"(v));
    return r;
}
__device__ __forceinline__ void fma2(unsigned long long& d, unsigned long long a, unsigned long long b) {
    asm("fma.rn.f32x2 %0, %1, %2, %0;" : "+l"(d) : "l"(a), "l"(b));
}

// ---------------- grid-wide barrier (all blocks co-resident by construction) ----------------
__device__ __forceinline__ void grid_barrier(unsigned& mygen) {
    __threadfence();
    __syncthreads();
    if (threadIdx.x == 0) {
        unsigned ticket = atomicAdd(&g_arrive, 1u);
        if (ticket == gridDim.x - 1) {
            g_arrive = 0;
            __threadfence();
            atomicAdd(&g_gen, 1u);          // release
        } else {
            while (*((volatile unsigned*)&g_gen) == mygen) { __nanosleep(32); }
        }
        __threadfence();
    }
    __syncthreads();
    mygen += 1;
}

__device__ __forceinline__ float sigf(float x) { return 1.0f / (1.0f + __expf(-x)); }

// ---------------- x-part GEMM (f32x2): g_xz[n][4u+g] = b[gH+u] + sum_k A[n][k]*W[gH+u][k] ----------------
// A: (NT,K) row-major. Output columns gate-interleaved. 128x128x16 tile, 256 thr, 8x8 reg tile as f32x2.
__global__ __launch_bounds__(256) void xz_gemm(
    const float* __restrict__ Aext, const float* __restrict__ W,
    const float* __restrict__ bias, int K, int ldw, int a_internal)
{
    const float* A = a_internal ? g_y0 : Aext;
    __shared__ float As[16][256];   // A values duplicated: As[k][2r]=As[k][2r+1]=A[m0+r][k]
    __shared__ float Bs[16][128];
    int tid = threadIdx.x;
    int m0 = blockIdx.x * 128;
    int n0 = blockIdx.y * 128;
    int tx = tid & 15, ty = tid >> 4;
    int lr = tid >> 2;            // 0..63
    int lk = (tid & 3) << 2;      // 0,4,8,12

    unsigned long long acc[8][4];
#pragma unroll
    for (int i = 0; i < 8; i++)
#pragma unroll
        for (int j = 0; j < 4; j++) acc[i][j] = 0ull;   // (0.f,0.f)

    for (int k0 = 0; k0 < K; k0 += 16) {
#pragma unroll
        for (int hh = 0; hh < 2; hh++) {
            int r = lr + hh * 64;
            float4 va = *(const float4*)&A[(size_t)(m0 + r) * K + k0 + lk];
            *(float2*)&As[lk + 0][2 * r] = make_float2(va.x, va.x);
            *(float2*)&As[lk + 1][2 * r] = make_float2(va.y, va.y);
            *(float2*)&As[lk + 2][2 * r] = make_float2(va.z, va.z);
            *(float2*)&As[lk + 3][2 * r] = make_float2(va.w, va.w);
            int jj = n0 + r;
            int jorig = (jj & 3) * Hv + (jj >> 2);     // interleaved col -> orig W row
            float4 vb = *(const float4*)&W[(size_t)jorig * ldw + k0 + lk];
            Bs[lk + 0][r] = vb.x; Bs[lk + 1][r] = vb.y; Bs[lk + 2][r] = vb.z; Bs[lk + 3][r] = vb.w;
        }
        __syncthreads();
#pragma unroll
        for (int k = 0; k < 16; k++) {
            ulonglong2 a01 = *(const ulonglong2*)&As[k][8 * ty];
            ulonglong2 a23 = *(const ulonglong2*)&As[k][8 * ty + 4];
            ulonglong2 a45 = *(const ulonglong2*)&As[k][128 + 8 * ty];
            ulonglong2 a67 = *(const ulonglong2*)&As[k][128 + 8 * ty + 4];
            ulonglong2 b03 = *(const ulonglong2*)&Bs[k][4 * tx];
            ulonglong2 b47 = *(const ulonglong2*)&Bs[k][64 + 4 * tx];
            unsigned long long au[8] = {a01.x, a01.y, a23.x, a23.y, a45.x, a45.y, a67.x, a67.y};
            unsigned long long bu[4] = {b03.x, b03.y, b47.x, b47.y};
#pragma unroll
            for (int i = 0; i < 8; i++)
#pragma unroll
                for (int j = 0; j < 4; j++) fma2(acc[i][j], au[i], bu[j]);
        }
        __syncthreads();
    }

    float bsv[8];
#pragma unroll
    for (int j = 0; j < 4; j++) {
        int jj = n0 + tx * 4 + j;
        bsv[j] = bias[(jj & 3) * Hv + (jj >> 2)];
        int jj2 = n0 + 64 + tx * 4 + j;
        bsv[4 + j] = bias[(jj2 & 3) * Hv + (jj2 >> 2)];
    }
#pragma unroll
    for (int i = 0; i < 8; i++) {
        int m = m0 + ((i < 4) ? (ty * 4 + i) : (64 + ty * 4 + (i - 4)));
        float* crow = &g_xz[(size_t)m * FH + n0];
#pragma unroll
        for (int jp = 0; jp < 4; jp++) {
            float2 v = unpk2(acc[i][jp]);
            int cbase = (jp < 2) ? (tx * 4 + jp * 2) : (64 + tx * 4 + (jp - 2) * 2);
            int jb = (jp < 2) ? (jp * 2) : (4 + (jp - 2) * 2);
            crow[cbase + 0] = v.x + bsv[jb + 0];
            crow[cbase + 1] = v.y + bsv[jb + 1];
        }
    }
}

// ---------------- persistent recurrence: weight-stationary, f32x2 inner loop ----------------
// 128 blocks x 256 threads, 1 block/SM (128 KB smem). Block: 8 units x 4 gates x all 64 batches.
// Weights resident in smem for the whole layer. h read from L2 (__ldcg), c in registers.
__global__ __launch_bounds__(RTHR) void lstm_rec(
    const float* __restrict__ W, int ldw, int coloff,
    float* __restrict__ yext, int y_internal)
{
    extern __shared__ float w_s[];    // [1024][32]: w_s[k][ul*4+g] = W[g*H + u0+ul][coloff+k]
    float* y = y_internal ? g_y0 : yext;
    int tid = threadIdx.x;
    int u0 = blockIdx.x * 8;
    int lane = tid & 31, wrp = tid >> 5;

    // one-time resident weight load (lane -> (ul,g) with ul=lane>>2, g=lane&3 => col c = lane)
    {
        int ul = lane >> 2, g = lane & 3;
        const float* wrow = W + (size_t)(g * Hv + u0 + ul) * ldw + coloff + wrp * 128;
#pragma unroll
        for (int i = 0; i < 32; i++) {
            float4 v = *(const float4*)(wrow + i * 4);
            int kb = wrp * 128 + i * 4;
            w_s[(kb + 0) * 32 + lane] = v.x;
            w_s[(kb + 1) * 32 + lane] = v.y;
            w_s[(kb + 2) * 32 + lane] = v.z;
            w_s[(kb + 3) * 32 + lane] = v.w;
        }
    }

    // zero h buffer 0 (initial state)
    for (int i = blockIdx.x * RTHR + tid; i < Hv * Bv; i += RBLK * RTHR)
        ((float*)g_hbuf)[i] = 0.0f;

    int ulc = lane & 7;               // unit within block
    int bp  = wrp * 4 + (lane >> 3);  // batch pair 0..31
    int b_0 = bp * 2;
    int u   = u0 + ulc;

    float cc0 = 0.0f, cc1 = 0.0f;
    unsigned mygen = *((volatile unsigned*)&g_gen);
    grid_barrier(mygen);              // covers zeroing + smem weight load (has __syncthreads)

    int p = 0;
    const size_t nrow0 = (size_t)b_0 * Tv;
    const float* wsp = w_s + ulc * 4;

    for (int t = 0; t < Tv; t++) {
        // init z with precomputed gate-interleaved x-part (+bias folded)
        const float* xz0 = &g_xz[(nrow0 + t) * FH + (size_t)u * 4];
        float4 xa = __ldcs((const float4*)xz0);
        float4 xb = __ldcs((const float4*)(xz0 + (size_t)Tv * FH));
        unsigned long long zA01 = pack2(xa.x, xa.y), zA23 = pack2(xa.z, xa.w);
        unsigned long long zB01 = pack2(xb.x, xb.y), zB23 = pack2(xb.z, xb.w);

        const float* hb = &g_hbuf[p][0][b_0];
#pragma unroll 1
        for (int kk = 0; kk < Hv; kk += 8) {
            float2 hr[8];
#pragma unroll
            for (int j = 0; j < 8; j++)
                hr[j] = __ldcg((const float2*)(hb + (size_t)(kk + j) * Bv));
#pragma unroll
            for (int j = 0; j < 8; j++) {
                unsigned long long ha = splat2(hr[j].x);
                unsigned long long hc = splat2(hr[j].y);
                ulonglong2 w2 = *(const ulonglong2*)(wsp + (size_t)(kk + j) * 32);
                fma2(zA01, ha, w2.x); fma2(zA23, ha, w2.y);
                fma2(zB01, hc, w2.x); fma2(zB23, hc, w2.y);
            }
        }

        float2 zif0 = unpk2(zA01), zog0 = unpk2(zA23);
        float2 zif1 = unpk2(zB01), zog1 = unpk2(zB23);
        float iv0 = sigf(zif0.x), fv0 = sigf(zif0.y), ov0 = sigf(zog0.x), gv0 = tanhf(zog0.y);
        cc0 = fv0 * cc0 + iv0 * gv0;
        float hv0 = ov0 * tanhf(cc0);
        float iv1 = sigf(zif1.x), fv1 = sigf(zif1.y), ov1 = sigf(zog1.x), gv1 = tanhf(zog1.y);
        cc1 = fv1 * cc1 + iv1 * gv1;
        float hv1 = ov1 * tanhf(cc1);

        *(float2*)&g_hbuf[p ^ 1][u][b_0] = make_float2(hv0, hv1);
        y[(size_t)b_0 * (Tv * Hv) + (size_t)t * Hv + u]       = hv0;
        y[(size_t)(b_0 + 1) * (Tv * Hv) + (size_t)t * Hv + u] = hv1;

        p ^= 1;
        grid_barrier(mygen);
    }
}

// ---------------- entry point ----------------
extern "C" void kernel_launch(void* const* d_in, const int* in_sizes, int n_in,
                              void* d_out, int out_size) {
    (void)in_sizes; (void)n_in; (void)out_size;
    const float* x  = (const float*)d_in[0];
    const float* W0 = (const float*)d_in[1];
    const float* b0 = (const float*)d_in[2];
    const float* W1 = (const float*)d_in[3];
    const float* b1 = (const float*)d_in[4];
    float* out = (float*)d_out;

    cudaFuncSetAttribute(lstm_rec, cudaFuncAttributeMaxDynamicSharedMemorySize, RSMEM);

    dim3 gemm_grid(NTv / 128, FH / 128);

    // ---- layer 0 ----
    xz_gemm<<<gemm_grid, 256>>>(x, W0, b0, Dv, Dv + Hv, 0);       // xz = x @ W0x^T + b0
    lstm_rec<<<RBLK, RTHR, RSMEM>>>(W0, Dv + Hv, Dv, out, 1);     // -> g_y0

    // ---- layer 1 ----
    xz_gemm<<<gemm_grid, 256>>>(x, W1, b1, Hv, 2 * Hv, 1);        // xz = y0 @ W1x^T + b1
    lstm_rec<<<RBLK, RTHR, RSMEM>>>(W1, 2 * Hv, Hv, out, 0);      // -> d_out
}